// round 3
// baseline (speedup 1.0000x reference)
#include <cuda_runtime.h>

#define MAXN 100000
#define MAXE 1600000

// Scratch (no allocations allowed — __device__ globals)
__device__ int   g_deg[MAXN];
__device__ int   g_start[MAXN + 1];
__device__ int   g_cursor[MAXN];
__device__ int   g_srcs[MAXE];
__device__ float g_x1[(size_t)MAXN * 128];
__device__ float g_Wt1[16384];   // k-major: Wt[k*128 + j] = W[j*128 + k]
__device__ float g_Wt2[16384];

__global__ void k_zero_deg(int n) {
    int i = blockIdx.x * blockDim.x + threadIdx.x;
    if (i < n) g_deg[i] = 0;
}

__global__ void k_hist(const int* __restrict__ dst, int E) {
    int i = blockIdx.x * blockDim.x + threadIdx.x;
    if (i < E) atomicAdd(&g_deg[dst[i]], 1);
}

// Single-block exclusive scan over g_deg -> g_start / g_cursor
__global__ void k_scan(int N, int E) {
    __shared__ int sh[1024];
    int t = threadIdx.x;
    int CH = (N + 1023) >> 10;
    int base = t * CH;
    int s = 0;
    for (int i = 0; i < CH; i++) {
        int id = base + i;
        if (id < N) s += g_deg[id];
    }
    sh[t] = s;
    __syncthreads();
    for (int off = 1; off < 1024; off <<= 1) {
        int v = (t >= off) ? sh[t - off] : 0;
        __syncthreads();
        sh[t] += v;
        __syncthreads();
    }
    int run = (t == 0) ? 0 : sh[t - 1];
    for (int i = 0; i < CH; i++) {
        int id = base + i;
        if (id < N) {
            g_start[id]  = run;
            g_cursor[id] = run;
            run += g_deg[id];
        }
    }
    if (t == 1023) g_start[N] = E;
}

__global__ void k_scatter(const int* __restrict__ src,
                          const int* __restrict__ dst, int E) {
    int i = blockIdx.x * blockDim.x + threadIdx.x;
    if (i < E) {
        int pos = atomicAdd(&g_cursor[dst[i]], 1);
        g_srcs[pos] = src[i];
    }
}

// Transpose both weight matrices to k-major (once per launch, tiny).
__global__ void k_transpose(const float* __restrict__ W1,
                            const float* __restrict__ W2) {
    int i = blockIdx.x * blockDim.x + threadIdx.x;  // 16384 threads
    int j = i >> 7, k = i & 127;
    g_Wt1[k * 128 + j] = W1[i];
    g_Wt2[k * 128 + j] = W2[i];
}

// Fused layer: warp processes a tile of 8 nodes.
// Phase 1 (gather): combined row (x + mean_neigh) per node -> smem.
// Phase 2 (GEMM): 8 rows x 128 cols, lane owns 4 cols, W read once per tile
//                 (k-major, coalesced __ldg, L1-resident).
__global__ void __launch_bounds__(256) k_layer(
        const float* __restrict__ xin_ext,
        float* __restrict__ out_ext,
        const float* __restrict__ b,
        int N, int layer) {
    __shared__ float srows[8][8][128];   // [warp][row][k]  32 KB

    const float* xin = (layer == 1) ? xin_ext : (const float*)g_x1;
    float*       out = (layer == 1) ? (float*)g_x1 : out_ext;
    const float* Wt  = (layer == 1) ? (const float*)g_Wt1 : (const float*)g_Wt2;

    int w = threadIdx.x >> 5, lane = threadIdx.x & 31;
    float4 breg = __ldg((const float4*)b + lane);

    int warpId = blockIdx.x * 8 + w;
    int nWarps = gridDim.x * 8;
    int nTiles = (N + 7) >> 3;

    for (int t = warpId; t < nTiles; t += nWarps) {
        int n0 = t << 3;
        int nrows = min(8, N - n0);

        // ---- Phase 1: gather ----
        for (int r = 0; r < nrows; r++) {
            int n = n0 + r;
            int beg = g_start[n], end = g_start[n + 1];
            float4 a0 = make_float4(0.f, 0.f, 0.f, 0.f);
            float4 a1 = make_float4(0.f, 0.f, 0.f, 0.f);
            for (int base = beg; base < end; base += 32) {
                int rem = end - base;
                int m = rem < 32 ? rem : 32;
                int idx = (lane < m) ? g_srcs[base + lane] : 0;
                int j = 0;
                for (; j + 1 < m; j += 2) {
                    int s0 = __shfl_sync(0xffffffffu, idx, j);
                    int s1 = __shfl_sync(0xffffffffu, idx, j + 1);
                    float4 v0 = __ldcs((const float4*)(xin + (size_t)s0 * 128) + lane);
                    float4 v1 = __ldcs((const float4*)(xin + (size_t)s1 * 128) + lane);
                    a0.x += v0.x; a0.y += v0.y; a0.z += v0.z; a0.w += v0.w;
                    a1.x += v1.x; a1.y += v1.y; a1.z += v1.z; a1.w += v1.w;
                }
                if (j < m) {
                    int s0 = __shfl_sync(0xffffffffu, idx, j);
                    float4 v0 = __ldcs((const float4*)(xin + (size_t)s0 * 128) + lane);
                    a0.x += v0.x; a0.y += v0.y; a0.z += v0.z; a0.w += v0.w;
                }
            }
            float inv = 1.0f / fmaxf((float)(end - beg), 1.0f);
            float4 f = __ldcs((const float4*)(xin + (size_t)n * 128) + lane);
            float4 comb;
            comb.x = f.x + (a0.x + a1.x) * inv;
            comb.y = f.y + (a0.y + a1.y) * inv;
            comb.z = f.z + (a0.z + a1.z) * inv;
            comb.w = f.w + (a0.w + a1.w) * inv;
            *(float4*)&srows[w][r][lane << 2] = comb;
        }
        __syncwarp();

        // ---- Phase 2: GEMM (8 rows x 4 cols per lane) ----
        float4 acc[8];
#pragma unroll
        for (int r = 0; r < 8; r++) acc[r] = breg;

#pragma unroll 2
        for (int k4 = 0; k4 < 128; k4 += 4) {
            float4 wv0 = __ldg((const float4*)(Wt + (size_t)(k4 + 0) * 128) + lane);
            float4 wv1 = __ldg((const float4*)(Wt + (size_t)(k4 + 1) * 128) + lane);
            float4 wv2 = __ldg((const float4*)(Wt + (size_t)(k4 + 2) * 128) + lane);
            float4 wv3 = __ldg((const float4*)(Wt + (size_t)(k4 + 3) * 128) + lane);
#pragma unroll
            for (int r = 0; r < 8; r++) {
                float4 a = *(const float4*)&srows[w][r][k4];
                acc[r].x += a.x * wv0.x; acc[r].y += a.x * wv0.y;
                acc[r].z += a.x * wv0.z; acc[r].w += a.x * wv0.w;
                acc[r].x += a.y * wv1.x; acc[r].y += a.y * wv1.y;
                acc[r].z += a.y * wv1.z; acc[r].w += a.y * wv1.w;
                acc[r].x += a.z * wv2.x; acc[r].y += a.z * wv2.y;
                acc[r].z += a.z * wv2.z; acc[r].w += a.z * wv2.w;
                acc[r].x += a.w * wv3.x; acc[r].y += a.w * wv3.y;
                acc[r].z += a.w * wv3.z; acc[r].w += a.w * wv3.w;
            }
        }

        for (int r = 0; r < nrows; r++) {
            float4 o = acc[r];
            if (layer == 1) {
                o.x = fmaxf(o.x, 0.f); o.y = fmaxf(o.y, 0.f);
                o.z = fmaxf(o.z, 0.f); o.w = fmaxf(o.w, 0.f);
            }
            *(float4*)(out + (size_t)(n0 + r) * 128 + (lane << 2)) = o;
        }
        __syncwarp();
    }
}

extern "C" void kernel_launch(void* const* d_in, const int* in_sizes, int n_in,
                              void* d_out, int out_size) {
    const float* feat = (const float*)d_in[0];
    const int*   src  = (const int*)d_in[1];
    const int*   dst  = (const int*)d_in[2];
    const float* W1   = (const float*)d_in[3];
    const float* b1   = (const float*)d_in[4];
    const float* W2   = (const float*)d_in[5];
    const float* b2   = (const float*)d_in[6];
    float* out = (float*)d_out;

    int N = in_sizes[0] / 128;
    int E = in_sizes[1];

    k_transpose<<<128, 128>>>(W1, W2);
    k_zero_deg<<<(N + 255) / 256, 256>>>(N);
    k_hist<<<(E + 255) / 256, 256>>>(dst, E);
    k_scan<<<1, 1024>>>(N, E);
    k_scatter<<<(E + 255) / 256, 256>>>(src, dst, E);

    k_layer<<<592, 256>>>(feat, nullptr, b1, N, 1);   // feat -> g_x1 (+ReLU)
    k_layer<<<592, 256>>>(nullptr, out, b2, N, 2);    // g_x1 -> out
}

// round 4
// speedup vs baseline: 1.5045x; 1.5045x over previous
#include <cuda_runtime.h>

#define MAXN 100000
#define MAXE 1600000
#define SCAN_B 1024
#define NBLK ((MAXN + SCAN_B - 1) / SCAN_B)

// Scratch (no allocations allowed — __device__ globals)
__device__ int   g_deg[MAXN];
__device__ int   g_start[MAXN + 1];
__device__ int   g_cursor[MAXN];
__device__ int   g_srcs[MAXE];
__device__ int   g_bsum[NBLK];
__device__ int   g_boff[NBLK];
__device__ float g_x1[(size_t)MAXN * 128];
__device__ float g_Wt1[16384];   // k-major: Wt[k*128 + j] = W[j*128 + k]
__device__ float g_Wt2[16384];

__global__ void k_zero_deg(int n) {
    int i = blockIdx.x * blockDim.x + threadIdx.x;
    if (i < n) g_deg[i] = 0;
}

__global__ void k_hist(const int* __restrict__ dst, int E) {
    int i = blockIdx.x * blockDim.x + threadIdx.x;
    if (i < E) atomicAdd(&g_deg[dst[i]], 1);
}

// ---- Hierarchical scan: phase 1 (per-block exclusive scan + block sums) ----
__global__ void k_scan1(int N) {
    __shared__ int sh[SCAN_B];
    int i = blockIdx.x * SCAN_B + threadIdx.x;
    int v = (i < N) ? g_deg[i] : 0;
    sh[threadIdx.x] = v;
    __syncthreads();
    for (int off = 1; off < SCAN_B; off <<= 1) {
        int t = (threadIdx.x >= off) ? sh[threadIdx.x - off] : 0;
        __syncthreads();
        sh[threadIdx.x] += t;
        __syncthreads();
    }
    if (i < N) g_start[i] = sh[threadIdx.x] - v;   // exclusive
    if (threadIdx.x == SCAN_B - 1) g_bsum[blockIdx.x] = sh[SCAN_B - 1];
}

// ---- phase 2: scan the (<=98) block sums ----
__global__ void k_scan2(int nb) {
    if (threadIdx.x == 0) {
        int run = 0;
        for (int i = 0; i < nb; i++) { int v = g_bsum[i]; g_boff[i] = run; run += v; }
    }
}

// ---- phase 3: add block offsets, init cursors ----
__global__ void k_scan3(int N, int E) {
    int i = blockIdx.x * SCAN_B + threadIdx.x;
    if (i < N) {
        int s = g_start[i] + g_boff[blockIdx.x];
        g_start[i]  = s;
        g_cursor[i] = s;
    }
    if (i == 0) g_start[N] = E;
}

__global__ void k_scatter(const int* __restrict__ src,
                          const int* __restrict__ dst, int E) {
    int i = blockIdx.x * blockDim.x + threadIdx.x;
    if (i < E) {
        int pos = atomicAdd(&g_cursor[dst[i]], 1);
        g_srcs[pos] = src[i];
    }
}

// Transpose both weight matrices to k-major (once per launch, tiny).
__global__ void k_transpose(const float* __restrict__ W1,
                            const float* __restrict__ W2) {
    int i = blockIdx.x * blockDim.x + threadIdx.x;  // 16384 threads
    int j = i >> 7, k = i & 127;
    g_Wt1[k * 128 + j] = W1[i];
    g_Wt2[k * 128 + j] = W2[i];
}

// Fused layer: warp processes a tile of 8 nodes.
// Phase 1 (gather): combined row (x + mean_neigh) per node -> smem (MLP=4).
// Phase 2 (GEMM): 8 rows x 128 cols, lane owns 4 cols, W k-major via __ldg.
__global__ void __launch_bounds__(256) k_layer(
        const float* __restrict__ xin_ext,
        float* __restrict__ out_ext,
        const float* __restrict__ b,
        int N, int layer) {
    __shared__ float srows[8][8][128];   // [warp][row][k]  32 KB

    const float* xin = (layer == 1) ? xin_ext : (const float*)g_x1;
    float*       out = (layer == 1) ? (float*)g_x1 : out_ext;
    const float* Wt  = (layer == 1) ? (const float*)g_Wt1 : (const float*)g_Wt2;

    int w = threadIdx.x >> 5, lane = threadIdx.x & 31;
    float4 breg = __ldg((const float4*)b + lane);

    int warpId = blockIdx.x * 8 + w;
    int nWarps = gridDim.x * 8;
    int nTiles = (N + 7) >> 3;

    for (int t = warpId; t < nTiles; t += nWarps) {
        int n0 = t << 3;
        int nrows = min(8, N - n0);

        // ---- Phase 1: gather ----
        for (int r = 0; r < nrows; r++) {
            int n = n0 + r;
            int beg = g_start[n], end = g_start[n + 1];
            float4 a0 = make_float4(0.f, 0.f, 0.f, 0.f);
            float4 a1 = make_float4(0.f, 0.f, 0.f, 0.f);
            float4 a2 = make_float4(0.f, 0.f, 0.f, 0.f);
            float4 a3 = make_float4(0.f, 0.f, 0.f, 0.f);
            for (int base = beg; base < end; base += 32) {
                int rem = end - base;
                int m = rem < 32 ? rem : 32;
                int idx = (lane < m) ? g_srcs[base + lane] : 0;
                int j = 0;
                for (; j + 3 < m; j += 4) {
                    int s0 = __shfl_sync(0xffffffffu, idx, j);
                    int s1 = __shfl_sync(0xffffffffu, idx, j + 1);
                    int s2 = __shfl_sync(0xffffffffu, idx, j + 2);
                    int s3 = __shfl_sync(0xffffffffu, idx, j + 3);
                    float4 v0 = __ldcs((const float4*)(xin + (size_t)s0 * 128) + lane);
                    float4 v1 = __ldcs((const float4*)(xin + (size_t)s1 * 128) + lane);
                    float4 v2 = __ldcs((const float4*)(xin + (size_t)s2 * 128) + lane);
                    float4 v3 = __ldcs((const float4*)(xin + (size_t)s3 * 128) + lane);
                    a0.x += v0.x; a0.y += v0.y; a0.z += v0.z; a0.w += v0.w;
                    a1.x += v1.x; a1.y += v1.y; a1.z += v1.z; a1.w += v1.w;
                    a2.x += v2.x; a2.y += v2.y; a2.z += v2.z; a2.w += v2.w;
                    a3.x += v3.x; a3.y += v3.y; a3.z += v3.z; a3.w += v3.w;
                }
                for (; j < m; j++) {
                    int s0 = __shfl_sync(0xffffffffu, idx, j);
                    float4 v0 = __ldcs((const float4*)(xin + (size_t)s0 * 128) + lane);
                    a0.x += v0.x; a0.y += v0.y; a0.z += v0.z; a0.w += v0.w;
                }
            }
            float inv = 1.0f / fmaxf((float)(end - beg), 1.0f);
            float4 f = __ldcs((const float4*)(xin + (size_t)n * 128) + lane);
            float4 comb;
            comb.x = f.x + (a0.x + a1.x + a2.x + a3.x) * inv;
            comb.y = f.y + (a0.y + a1.y + a2.y + a3.y) * inv;
            comb.z = f.z + (a0.z + a1.z + a2.z + a3.z) * inv;
            comb.w = f.w + (a0.w + a1.w + a2.w + a3.w) * inv;
            *(float4*)&srows[w][r][lane << 2] = comb;
        }
        __syncwarp();

        // ---- Phase 2: GEMM (8 rows x 4 cols per lane) ----
        float4 acc[8];
#pragma unroll
        for (int r = 0; r < 8; r++) acc[r] = breg;

#pragma unroll 2
        for (int k4 = 0; k4 < 128; k4 += 4) {
            float4 wv0 = __ldg((const float4*)(Wt + (size_t)(k4 + 0) * 128) + lane);
            float4 wv1 = __ldg((const float4*)(Wt + (size_t)(k4 + 1) * 128) + lane);
            float4 wv2 = __ldg((const float4*)(Wt + (size_t)(k4 + 2) * 128) + lane);
            float4 wv3 = __ldg((const float4*)(Wt + (size_t)(k4 + 3) * 128) + lane);
#pragma unroll
            for (int r = 0; r < 8; r++) {
                float4 a = *(const float4*)&srows[w][r][k4];
                acc[r].x += a.x * wv0.x; acc[r].y += a.x * wv0.y;
                acc[r].z += a.x * wv0.z; acc[r].w += a.x * wv0.w;
                acc[r].x += a.y * wv1.x; acc[r].y += a.y * wv1.y;
                acc[r].z += a.y * wv1.z; acc[r].w += a.y * wv1.w;
                acc[r].x += a.z * wv2.x; acc[r].y += a.z * wv2.y;
                acc[r].z += a.z * wv2.z; acc[r].w += a.z * wv2.w;
                acc[r].x += a.w * wv3.x; acc[r].y += a.w * wv3.y;
                acc[r].z += a.w * wv3.z; acc[r].w += a.w * wv3.w;
            }
        }

        for (int r = 0; r < nrows; r++) {
            float4 o = acc[r];
            if (layer == 1) {
                o.x = fmaxf(o.x, 0.f); o.y = fmaxf(o.y, 0.f);
                o.z = fmaxf(o.z, 0.f); o.w = fmaxf(o.w, 0.f);
            }
            *(float4*)(out + (size_t)(n0 + r) * 128 + (lane << 2)) = o;
        }
        __syncwarp();
    }
}

extern "C" void kernel_launch(void* const* d_in, const int* in_sizes, int n_in,
                              void* d_out, int out_size) {
    const float* feat = (const float*)d_in[0];
    const int*   src  = (const int*)d_in[1];
    const int*   dst  = (const int*)d_in[2];
    const float* W1   = (const float*)d_in[3];
    const float* b1   = (const float*)d_in[4];
    const float* W2   = (const float*)d_in[5];
    const float* b2   = (const float*)d_in[6];
    float* out = (float*)d_out;

    int N = in_sizes[0] / 128;
    int E = in_sizes[1];
    int nb = (N + SCAN_B - 1) / SCAN_B;

    k_transpose<<<128, 128>>>(W1, W2);
    k_zero_deg<<<(N + 255) / 256, 256>>>(N);
    k_hist<<<(E + 255) / 256, 256>>>(dst, E);
    k_scan1<<<nb, SCAN_B>>>(N);
    k_scan2<<<1, 32>>>(nb);
    k_scan3<<<nb, SCAN_B>>>(N, E);
    k_scatter<<<(E + 255) / 256, 256>>>(src, dst, E);

    k_layer<<<592, 256>>>(feat, nullptr, b1, N, 1);   // feat -> g_x1 (+ReLU)
    k_layer<<<592, 256>>>(nullptr, out, b2, N, 2);    // g_x1 -> out
}

// round 5
// speedup vs baseline: 2.0049x; 1.3326x over previous
#include <cuda_runtime.h>

#define MAXN 100000
#define MAXE 1600000
#define SCAN_B 1024

// Scratch (no allocations allowed — __device__ globals)
__device__ int    g_deg[MAXN];
__device__ int    g_start[MAXN + 1];
__device__ int    g_cursor[MAXN];
__device__ int    g_srcs[MAXE];
__device__ int    g_bsum[128];
__device__ int    g_boff[128];
__device__ int    g_scan_ctr;
__device__ float  g_x1[(size_t)MAXN * 128];
// Interleaved k-pair weights: g_Wi[t*128 + c] = (W[c][2t], W[c][2t+1])
__device__ float2 g_W1i[8192];
__device__ float2 g_W2i[8192];

__device__ __forceinline__ void fma2(unsigned long long& d,
                                     unsigned long long a,
                                     unsigned long long b) {
    asm("fma.rn.f32x2 %0, %1, %2, %0;" : "+l"(d) : "l"(a), "l"(b));
}

// prep: interleave weights + zero degree array + zero scan counter
__global__ void k_prep(const float* __restrict__ W1,
                       const float* __restrict__ W2, int N) {
    int i = blockIdx.x * blockDim.x + threadIdx.x;
    if (i < 8192) {
        int t = i >> 7, c = i & 127;
        g_W1i[i] = make_float2(W1[c * 128 + 2 * t], W1[c * 128 + 2 * t + 1]);
        g_W2i[i] = make_float2(W2[c * 128 + 2 * t], W2[c * 128 + 2 * t + 1]);
    }
    for (int j = i; j < N; j += gridDim.x * blockDim.x) g_deg[j] = 0;
    if (i == 0) g_scan_ctr = 0;
}

__global__ void k_hist(const int* __restrict__ dst, int E) {
    int i = blockIdx.x * blockDim.x + threadIdx.x;
    if (i < E) atomicAdd(&g_deg[dst[i]], 1);
}

// per-block exclusive scan + block sums; last finished block scans block sums
__global__ void k_scan1(int N) {
    __shared__ int sh[SCAN_B];
    __shared__ int isLast;
    int i = blockIdx.x * SCAN_B + threadIdx.x;
    int v = (i < N) ? g_deg[i] : 0;
    sh[threadIdx.x] = v;
    __syncthreads();
    for (int off = 1; off < SCAN_B; off <<= 1) {
        int t = (threadIdx.x >= off) ? sh[threadIdx.x - off] : 0;
        __syncthreads();
        sh[threadIdx.x] += t;
        __syncthreads();
    }
    if (i < N) g_start[i] = sh[threadIdx.x] - v;   // exclusive partial
    if (threadIdx.x == SCAN_B - 1) g_bsum[blockIdx.x] = sh[SCAN_B - 1];
    __threadfence();
    __syncthreads();
    if (threadIdx.x == 0)
        isLast = (atomicAdd(&g_scan_ctr, 1) == (int)gridDim.x - 1);
    __syncthreads();
    if (isLast && threadIdx.x == 0) {
        int run = 0;
        for (int k = 0; k < (int)gridDim.x; k++) {
            int t = g_bsum[k]; g_boff[k] = run; run += t;
        }
        __threadfence();
    }
}

// add block offsets, init cursors
__global__ void k_scan3(int N, int E) {
    int i = blockIdx.x * SCAN_B + threadIdx.x;
    if (i < N) {
        int s = g_start[i] + g_boff[blockIdx.x];
        g_start[i]  = s;
        g_cursor[i] = s;
    }
    if (i == 0) g_start[N] = E;
}

__global__ void k_scatter(const int* __restrict__ src,
                          const int* __restrict__ dst, int E) {
    int i = blockIdx.x * blockDim.x + threadIdx.x;
    if (i < E) {
        int pos = atomicAdd(&g_cursor[dst[i]], 1);
        g_srcs[pos] = src[i];
    }
}

// Fused layer. Warp tile = 8 nodes.
// Gather: mean of neighbor rows + self -> smem row buffer.
// GEMM: packed fma.rn.f32x2, even/odd-k partial sums in the two lanes.
// W staged in shared memory once per block (interleaved k-pair layout).
__global__ void __launch_bounds__(256, 2) k_layer(
        const float* __restrict__ xin_ext,
        float* __restrict__ out_ext,
        const float* __restrict__ b,
        int N, int layer) {
    extern __shared__ float smem[];
    unsigned long long* Wsh = (unsigned long long*)smem;  // 8192 ull = 64 KB
    float* srows = smem + 16384;                          // 8*8*128 f = 32 KB

    const float* xin = (layer == 1) ? xin_ext : (const float*)g_x1;
    float*       out = (layer == 1) ? (float*)g_x1 : out_ext;
    const float2* Wi = (layer == 1) ? g_W1i : g_W2i;

    for (int i = threadIdx.x; i < 8192; i += 256)
        ((float2*)Wsh)[i] = Wi[i];
    __syncthreads();

    int w = threadIdx.x >> 5, lane = threadIdx.x & 31;
    const float4 bb = __ldg((const float4*)b + lane);
    unsigned long long binit[4];
    binit[0] = (unsigned long long)__float_as_uint(bb.x);
    binit[1] = (unsigned long long)__float_as_uint(bb.y);
    binit[2] = (unsigned long long)__float_as_uint(bb.z);
    binit[3] = (unsigned long long)__float_as_uint(bb.w);

    float* myrows = srows + w * (8 * 128);

    int warpId = blockIdx.x * 8 + w;
    int nWarps = gridDim.x * 8;
    int nTiles = (N + 7) >> 3;

    for (int t = warpId; t < nTiles; t += nWarps) {
        int n0 = t << 3;
        int nrows = min(8, N - n0);

        // ---- gather ----
        for (int r = 0; r < nrows; r++) {
            int n = n0 + r;
            int beg = g_start[n], end = g_start[n + 1];
            float4 a0 = make_float4(0.f, 0.f, 0.f, 0.f);
            float4 a1 = make_float4(0.f, 0.f, 0.f, 0.f);
            float4 a2 = make_float4(0.f, 0.f, 0.f, 0.f);
            float4 a3 = make_float4(0.f, 0.f, 0.f, 0.f);
            for (int base = beg; base < end; base += 32) {
                int rem = end - base;
                int m = rem < 32 ? rem : 32;
                int idx = (lane < m) ? g_srcs[base + lane] : 0;
                int j = 0;
                for (; j + 3 < m; j += 4) {
                    int s0 = __shfl_sync(0xffffffffu, idx, j);
                    int s1 = __shfl_sync(0xffffffffu, idx, j + 1);
                    int s2 = __shfl_sync(0xffffffffu, idx, j + 2);
                    int s3 = __shfl_sync(0xffffffffu, idx, j + 3);
                    float4 v0 = *((const float4*)(xin + (size_t)s0 * 128) + lane);
                    float4 v1 = *((const float4*)(xin + (size_t)s1 * 128) + lane);
                    float4 v2 = *((const float4*)(xin + (size_t)s2 * 128) + lane);
                    float4 v3 = *((const float4*)(xin + (size_t)s3 * 128) + lane);
                    a0.x += v0.x; a0.y += v0.y; a0.z += v0.z; a0.w += v0.w;
                    a1.x += v1.x; a1.y += v1.y; a1.z += v1.z; a1.w += v1.w;
                    a2.x += v2.x; a2.y += v2.y; a2.z += v2.z; a2.w += v2.w;
                    a3.x += v3.x; a3.y += v3.y; a3.z += v3.z; a3.w += v3.w;
                }
                for (; j < m; j++) {
                    int s0 = __shfl_sync(0xffffffffu, idx, j);
                    float4 v0 = *((const float4*)(xin + (size_t)s0 * 128) + lane);
                    a0.x += v0.x; a0.y += v0.y; a0.z += v0.z; a0.w += v0.w;
                }
            }
            float inv = 1.0f / fmaxf((float)(end - beg), 1.0f);
            float4 f = *((const float4*)(xin + (size_t)n * 128) + lane);
            float4 comb;
            comb.x = f.x + (a0.x + a1.x + a2.x + a3.x) * inv;
            comb.y = f.y + (a0.y + a1.y + a2.y + a3.y) * inv;
            comb.z = f.z + (a0.z + a1.z + a2.z + a3.z) * inv;
            comb.w = f.w + (a0.w + a1.w + a2.w + a3.w) * inv;
            *(float4*)&myrows[r * 128 + (lane << 2)] = comb;
        }
        __syncwarp();

        // ---- GEMM: 8 rows x 4 cols per lane, packed f32x2 even/odd-k ----
        unsigned long long acc[8][4];
#pragma unroll
        for (int r = 0; r < 8; r++) {
            acc[r][0] = binit[0]; acc[r][1] = binit[1];
            acc[r][2] = binit[2]; acc[r][3] = binit[3];
        }

#pragma unroll 2
        for (int k4 = 0; k4 < 128; k4 += 4) {
            const unsigned long long* w0 = Wsh + (k4 >> 1) * 128 + (lane << 2);
            const unsigned long long* w1 = w0 + 128;
            unsigned long long wa0 = w0[0], wa1 = w0[1], wa2 = w0[2], wa3 = w0[3];
            unsigned long long wb0 = w1[0], wb1 = w1[1], wb2 = w1[2], wb3 = w1[3];
#pragma unroll
            for (int r = 0; r < 8; r++) {
                ulonglong2 av = *(const ulonglong2*)&myrows[r * 128 + k4];
                fma2(acc[r][0], av.x, wa0);
                fma2(acc[r][1], av.x, wa1);
                fma2(acc[r][2], av.x, wa2);
                fma2(acc[r][3], av.x, wa3);
                fma2(acc[r][0], av.y, wb0);
                fma2(acc[r][1], av.y, wb1);
                fma2(acc[r][2], av.y, wb2);
                fma2(acc[r][3], av.y, wb3);
            }
        }

        for (int r = 0; r < nrows; r++) {
            float4 o;
            o.x = __uint_as_float((unsigned)acc[r][0]) + __uint_as_float((unsigned)(acc[r][0] >> 32));
            o.y = __uint_as_float((unsigned)acc[r][1]) + __uint_as_float((unsigned)(acc[r][1] >> 32));
            o.z = __uint_as_float((unsigned)acc[r][2]) + __uint_as_float((unsigned)(acc[r][2] >> 32));
            o.w = __uint_as_float((unsigned)acc[r][3]) + __uint_as_float((unsigned)(acc[r][3] >> 32));
            if (layer == 1) {
                o.x = fmaxf(o.x, 0.f); o.y = fmaxf(o.y, 0.f);
                o.z = fmaxf(o.z, 0.f); o.w = fmaxf(o.w, 0.f);
            }
            *(float4*)(out + (size_t)(n0 + r) * 128 + (lane << 2)) = o;
        }
        __syncwarp();
    }
}

extern "C" void kernel_launch(void* const* d_in, const int* in_sizes, int n_in,
                              void* d_out, int out_size) {
    const float* feat = (const float*)d_in[0];
    const int*   src  = (const int*)d_in[1];
    const int*   dst  = (const int*)d_in[2];
    const float* W1   = (const float*)d_in[3];
    const float* b1   = (const float*)d_in[4];
    const float* W2   = (const float*)d_in[5];
    const float* b2   = (const float*)d_in[6];
    float* out = (float*)d_out;

    int N = in_sizes[0] / 128;
    int E = in_sizes[1];
    int nb = (N + SCAN_B - 1) / SCAN_B;

    size_t smem = (size_t)(64 * 1024 + 32 * 1024);
    cudaFuncSetAttribute((const void*)k_layer,
                         cudaFuncAttributeMaxDynamicSharedMemorySize, (int)smem);

    k_prep<<<98, 1024>>>(W1, W2, N);                 // #0
    k_hist<<<(E + 255) / 256, 256>>>(dst, E);        // #1
    k_scan1<<<nb, SCAN_B>>>(N);                      // #2 (scan2 fused)
    k_scan3<<<nb, SCAN_B>>>(N, E);                   // #3
    k_scatter<<<(E + 255) / 256, 256>>>(src, dst, E);// #4
    k_layer<<<296, 256, smem>>>(feat, nullptr, b1, N, 1);  // #5 (profiled)
    k_layer<<<296, 256, smem>>>(nullptr, out, b2, N, 2);   // #6
}

// round 6
// speedup vs baseline: 2.0600x; 1.0275x over previous
#include <cuda_runtime.h>

#define MAXN 100000
#define MAXE 1600000
#define SCAN_B 1024

// Scratch (no allocations allowed — __device__ globals)
__device__ int    g_deg[MAXN];
__device__ int    g_start[MAXN + 1];
__device__ int    g_cursor[MAXN];
__device__ int    g_srcs[MAXE];
__device__ int    g_bsum[128];
__device__ int    g_boff[128];
__device__ int    g_scan_ctr;
__device__ float  g_x1[(size_t)MAXN * 128];
// Interleaved k-pair weights: g_Wi[t*128 + c] = (W[c][2t], W[c][2t+1])
__device__ float2 g_W1i[8192];
__device__ float2 g_W2i[8192];

__device__ __forceinline__ void fma2(unsigned long long& d,
                                     unsigned long long a,
                                     unsigned long long b) {
    asm("fma.rn.f32x2 %0, %1, %2, %0;" : "+l"(d) : "l"(a), "l"(b));
}
__device__ __forceinline__ void add2(unsigned long long& d, unsigned long long a) {
    asm("add.rn.f32x2 %0, %0, %1;" : "+l"(d) : "l"(a));
}
__device__ __forceinline__ unsigned long long pack2(float lo, float hi) {
    unsigned long long r;
    asm("mov.b64 %0, {%1, %2};" : "=l"(r) : "f"(lo), "f"(hi));
    return r;
}

// prep: interleave weights + zero degree array + zero scan counter
__global__ void k_prep(const float* __restrict__ W1,
                       const float* __restrict__ W2, int N) {
    int i = blockIdx.x * blockDim.x + threadIdx.x;
    if (i < 8192) {
        int t = i >> 7, c = i & 127;
        g_W1i[i] = make_float2(W1[c * 128 + 2 * t], W1[c * 128 + 2 * t + 1]);
        g_W2i[i] = make_float2(W2[c * 128 + 2 * t], W2[c * 128 + 2 * t + 1]);
    }
    for (int j = i; j < N; j += gridDim.x * blockDim.x) g_deg[j] = 0;
    if (i == 0) g_scan_ctr = 0;
}

__global__ void k_hist(const int* __restrict__ dst, int E) {
    int i = blockIdx.x * blockDim.x + threadIdx.x;
    if (i < E) atomicAdd(&g_deg[dst[i]], 1);
}

// per-block exclusive scan + block sums; last finished block scans block sums
__global__ void k_scan1(int N) {
    __shared__ int sh[SCAN_B];
    __shared__ int isLast;
    int i = blockIdx.x * SCAN_B + threadIdx.x;
    int v = (i < N) ? g_deg[i] : 0;
    sh[threadIdx.x] = v;
    __syncthreads();
    for (int off = 1; off < SCAN_B; off <<= 1) {
        int t = (threadIdx.x >= off) ? sh[threadIdx.x - off] : 0;
        __syncthreads();
        sh[threadIdx.x] += t;
        __syncthreads();
    }
    if (i < N) g_start[i] = sh[threadIdx.x] - v;   // exclusive partial
    if (threadIdx.x == SCAN_B - 1) g_bsum[blockIdx.x] = sh[SCAN_B - 1];
    __threadfence();
    __syncthreads();
    if (threadIdx.x == 0)
        isLast = (atomicAdd(&g_scan_ctr, 1) == (int)gridDim.x - 1);
    __syncthreads();
    if (isLast && threadIdx.x == 0) {
        int run = 0;
        for (int k = 0; k < (int)gridDim.x; k++) {
            int t = g_bsum[k]; g_boff[k] = run; run += t;
        }
        __threadfence();
    }
}

// add block offsets, init cursors
__global__ void k_scan3(int N, int E) {
    int i = blockIdx.x * SCAN_B + threadIdx.x;
    if (i < N) {
        int s = g_start[i] + g_boff[blockIdx.x];
        g_start[i]  = s;
        g_cursor[i] = s;
    }
    if (i == 0) g_start[N] = E;
}

__global__ void k_scatter(const int* __restrict__ src,
                          const int* __restrict__ dst, int E) {
    int i = blockIdx.x * blockDim.x + threadIdx.x;
    if (i < E) {
        int pos = atomicAdd(&g_cursor[dst[i]], 1);
        g_srcs[pos] = src[i];
    }
}

// Fused layer. Warp tile = 8 nodes.
// Gather: mean of neighbor rows + self -> smem row buffer (packed f32x2 adds).
// GEMM: packed fma.rn.f32x2; even/odd-k partial sums live in the two f32x2
// lanes. Lane owns cols {2L, 2L+1, 64+2L, 64+2L+1} -> every W smem read is a
// conflict-free LDS.128 (contiguous 512B half-row per warp).
__global__ void __launch_bounds__(256, 2) k_layer(
        const float* __restrict__ xin_ext,
        float* __restrict__ out_ext,
        const float* __restrict__ b,
        int N, int layer) {
    extern __shared__ float smem[];
    unsigned long long* Wsh = (unsigned long long*)smem;  // 8192 ull = 64 KB
    float* srows = smem + 16384;                          // 8*8*128 f = 32 KB

    const float* xin = (layer == 1) ? xin_ext : (const float*)g_x1;
    float*       out = (layer == 1) ? (float*)g_x1 : out_ext;
    const float2* Wi = (layer == 1) ? g_W1i : g_W2i;

    for (int i = threadIdx.x; i < 8192; i += 256)
        ((float2*)Wsh)[i] = Wi[i];
    __syncthreads();

    int w = threadIdx.x >> 5, lane = threadIdx.x & 31;

    // bias for owned cols: {2L, 2L+1, 64+2L, 64+2L+1}; packed (bias, 0)
    float2 blo = __ldg((const float2*)b + lane);
    float2 bhi = __ldg((const float2*)b + 32 + lane);
    unsigned long long binit[4];
    binit[0] = (unsigned long long)__float_as_uint(blo.x);
    binit[1] = (unsigned long long)__float_as_uint(blo.y);
    binit[2] = (unsigned long long)__float_as_uint(bhi.x);
    binit[3] = (unsigned long long)__float_as_uint(bhi.y);

    float* myrows = srows + w * (8 * 128);

    int warpId = blockIdx.x * 8 + w;
    int nWarps = gridDim.x * 8;
    int nTiles = (N + 7) >> 3;

    for (int t = warpId; t < nTiles; t += nWarps) {
        int n0 = t << 3;
        int nrows = min(8, N - n0);

        // ---- gather ----
        for (int r = 0; r < nrows; r++) {
            int n = n0 + r;
            int beg = g_start[n], end = g_start[n + 1];
            ulonglong2 a0 = {0ull, 0ull}, a1 = {0ull, 0ull};
            ulonglong2 a2 = {0ull, 0ull}, a3 = {0ull, 0ull};
            for (int base = beg; base < end; base += 32) {
                int rem = end - base;
                int m = rem < 32 ? rem : 32;
                int idx = (lane < m) ? g_srcs[base + lane] : 0;
                int j = 0;
                for (; j + 3 < m; j += 4) {
                    int s0 = __shfl_sync(0xffffffffu, idx, j);
                    int s1 = __shfl_sync(0xffffffffu, idx, j + 1);
                    int s2 = __shfl_sync(0xffffffffu, idx, j + 2);
                    int s3 = __shfl_sync(0xffffffffu, idx, j + 3);
                    ulonglong2 v0 = *((const ulonglong2*)(xin + (size_t)s0 * 128) + lane);
                    ulonglong2 v1 = *((const ulonglong2*)(xin + (size_t)s1 * 128) + lane);
                    ulonglong2 v2 = *((const ulonglong2*)(xin + (size_t)s2 * 128) + lane);
                    ulonglong2 v3 = *((const ulonglong2*)(xin + (size_t)s3 * 128) + lane);
                    add2(a0.x, v0.x); add2(a0.y, v0.y);
                    add2(a1.x, v1.x); add2(a1.y, v1.y);
                    add2(a2.x, v2.x); add2(a2.y, v2.y);
                    add2(a3.x, v3.x); add2(a3.y, v3.y);
                }
                for (; j < m; j++) {
                    int s0 = __shfl_sync(0xffffffffu, idx, j);
                    ulonglong2 v0 = *((const ulonglong2*)(xin + (size_t)s0 * 128) + lane);
                    add2(a0.x, v0.x); add2(a0.y, v0.y);
                }
            }
            // reduce chains, combine with self: comb = self + sum * inv
            add2(a0.x, a1.x); add2(a2.x, a3.x); add2(a0.x, a2.x);
            add2(a0.y, a1.y); add2(a2.y, a3.y); add2(a0.y, a2.y);
            float inv = 1.0f / fmaxf((float)(end - beg), 1.0f);
            unsigned long long inv2 = pack2(inv, inv);
            ulonglong2 f = *((const ulonglong2*)(xin + (size_t)n * 128) + lane);
            fma2(f.x, a0.x, inv2);
            fma2(f.y, a0.y, inv2);
            *(ulonglong2*)&myrows[r * 128 + (lane << 2)] = f;
        }
        __syncwarp();

        // ---- GEMM: 8 rows x 4 cols per lane, packed f32x2 even/odd-k ----
        unsigned long long acc[8][4];
#pragma unroll
        for (int r = 0; r < 8; r++) {
            acc[r][0] = binit[0]; acc[r][1] = binit[1];
            acc[r][2] = binit[2]; acc[r][3] = binit[3];
        }

#pragma unroll 4
        for (int t2 = 0; t2 < 64; t2 += 2) {
            // conflict-free: lane*2 float2 within contiguous 512B half-rows
            ulonglong2 wAlo = *(const ulonglong2*)(Wsh + (size_t)t2 * 128 + (lane << 1));
            ulonglong2 wAhi = *(const ulonglong2*)(Wsh + (size_t)t2 * 128 + 64 + (lane << 1));
            ulonglong2 wBlo = *(const ulonglong2*)(Wsh + (size_t)(t2 + 1) * 128 + (lane << 1));
            ulonglong2 wBhi = *(const ulonglong2*)(Wsh + (size_t)(t2 + 1) * 128 + 64 + (lane << 1));
#pragma unroll
            for (int r = 0; r < 8; r++) {
                // broadcast: k-pairs t2 (av.x) and t2+1 (av.y)
                ulonglong2 av = *(const ulonglong2*)&myrows[r * 128 + (t2 << 1)];
                fma2(acc[r][0], av.x, wAlo.x);
                fma2(acc[r][1], av.x, wAlo.y);
                fma2(acc[r][2], av.x, wAhi.x);
                fma2(acc[r][3], av.x, wAhi.y);
                fma2(acc[r][0], av.y, wBlo.x);
                fma2(acc[r][1], av.y, wBlo.y);
                fma2(acc[r][2], av.y, wBhi.x);
                fma2(acc[r][3], av.y, wBhi.y);
            }
        }

        for (int r = 0; r < nrows; r++) {
            float2 olo, ohi;
            olo.x = __uint_as_float((unsigned)acc[r][0]) + __uint_as_float((unsigned)(acc[r][0] >> 32));
            olo.y = __uint_as_float((unsigned)acc[r][1]) + __uint_as_float((unsigned)(acc[r][1] >> 32));
            ohi.x = __uint_as_float((unsigned)acc[r][2]) + __uint_as_float((unsigned)(acc[r][2] >> 32));
            ohi.y = __uint_as_float((unsigned)acc[r][3]) + __uint_as_float((unsigned)(acc[r][3] >> 32));
            if (layer == 1) {
                olo.x = fmaxf(olo.x, 0.f); olo.y = fmaxf(olo.y, 0.f);
                ohi.x = fmaxf(ohi.x, 0.f); ohi.y = fmaxf(ohi.y, 0.f);
            }
            float* orow = out + (size_t)(n0 + r) * 128;
            *((float2*)orow + lane)      = olo;
            *((float2*)orow + 32 + lane) = ohi;
        }
        __syncwarp();
    }
}

extern "C" void kernel_launch(void* const* d_in, const int* in_sizes, int n_in,
                              void* d_out, int out_size) {
    const float* feat = (const float*)d_in[0];
    const int*   src  = (const int*)d_in[1];
    const int*   dst  = (const int*)d_in[2];
    const float* W1   = (const float*)d_in[3];
    const float* b1   = (const float*)d_in[4];
    const float* W2   = (const float*)d_in[5];
    const float* b2   = (const float*)d_in[6];
    float* out = (float*)d_out;

    int N = in_sizes[0] / 128;
    int E = in_sizes[1];
    int nb = (N + SCAN_B - 1) / SCAN_B;

    size_t smem = (size_t)(64 * 1024 + 32 * 1024);
    cudaFuncSetAttribute((const void*)k_layer,
                         cudaFuncAttributeMaxDynamicSharedMemorySize, (int)smem);

    k_prep<<<98, 1024>>>(W1, W2, N);
    k_hist<<<(E + 255) / 256, 256>>>(dst, E);
    k_scan1<<<nb, SCAN_B>>>(N);
    k_scan3<<<nb, SCAN_B>>>(N, E);
    k_scatter<<<(E + 255) / 256, 256>>>(src, dst, E);
    k_layer<<<296, 256, smem>>>(feat, nullptr, b1, N, 1);
    k_layer<<<296, 256, smem>>>(nullptr, out, b2, N, 2);
}